// round 9
// baseline (speedup 1.0000x reference)
#include <cuda_runtime.h>
#include <cuda.h>
#include <cuda_bf16.h>
#include <cstdint>

#define NB   8
#define NC   512
#define NHW  4096
#define NQKV 1536

#define KSTEP   64                      // K elems per stage = 128B rows (SW128)
#define KTILES  (NC / KSTEP)            // 8
#define TM      192                     // M tile rows (3 warp rows of 64)
#define MTILES  ((NHW + TM - 1) / TM)   // 22 (padded; TMA zero-fills OOB)
#define OPA     (TM * 128)              // A operand tile: 192 rows x 128B = 24KB
#define OPBB    (128 * 128)             // B operand tile: 128 rows x 128B = 16KB
#define STAGEB  (2 * OPA + 2 * OPBB)    // Ah, Al, Bh, Bl = 80KB
#define NST     2
#define DSMEM   (NST * STAGEB + 1024)   // 160KB + align slack
#define NCONS   12                      // consumer warps (3m x 4n)

// ---------------- scratch (__device__ globals; no allocs allowed) ----------------
__device__ float g_qkv[(size_t)NB * NHW * NQKV];
__device__ float g_part[NB * 128 * 1024];
__device__ float g_s[NB * 1024];

__device__ __align__(16) __nv_bfloat16 g_xh[(size_t)NB * NHW * NC];
__device__ __align__(16) __nv_bfloat16 g_xl[(size_t)NB * NHW * NC];
__device__ __align__(16) __nv_bfloat16 g_wqh[(size_t)NQKV * NC];
__device__ __align__(16) __nv_bfloat16 g_wql[(size_t)NQKV * NC];
__device__ __align__(16) __nv_bfloat16 g_woh[(size_t)NC * NC];
__device__ __align__(16) __nv_bfloat16 g_wol[(size_t)NC * NC];
__device__ __align__(16) __nv_bfloat16 g_qah[(size_t)NB * NHW * NC];
__device__ __align__(16) __nv_bfloat16 g_qal[(size_t)NB * NHW * NC];

// ---------------------------------------------------------------------------
// PTX helpers (TMA / mbarrier / mma / ldmatrix)
// ---------------------------------------------------------------------------
__device__ __forceinline__ uint32_t cvta_s(const void* p) {
    return (uint32_t)__cvta_generic_to_shared(p);
}
__device__ __forceinline__ void mbar_init(uint32_t a, uint32_t c) {
    asm volatile("mbarrier.init.shared.b64 [%0], %1;" :: "r"(a), "r"(c) : "memory");
}
__device__ __forceinline__ void mbar_expect(uint32_t a, uint32_t tx) {
    asm volatile("mbarrier.arrive.expect_tx.shared.b64 _, [%0], %1;" :: "r"(a), "r"(tx) : "memory");
}
__device__ __forceinline__ void mbar_arrive(uint32_t a) {
    asm volatile("mbarrier.arrive.shared.b64 _, [%0];" :: "r"(a) : "memory");
}
__device__ __forceinline__ void mbar_wait(uint32_t a, uint32_t ph) {
    asm volatile(
        "{\n\t.reg .pred P;\n"
        "W%=:\n\tmbarrier.try_wait.parity.shared.b64 P, [%0], %1, 0x989680;\n"
        "\t@P bra D%=;\n\tbra W%=;\nD%=:\n\t}"
        :: "r"(a), "r"(ph) : "memory");
}
__device__ __forceinline__ void tma3d(uint32_t sa, const CUtensorMap* tm,
                                      int cx, int cy, int cz, uint32_t mb) {
    asm volatile(
        "cp.async.bulk.tensor.3d.shared::cta.global.tile.mbarrier::complete_tx::bytes "
        "[%0], [%1, {%2, %3, %4}], [%5];"
        :: "r"(sa), "l"(tm), "r"(cx), "r"(cy), "r"(cz), "r"(mb) : "memory");
}
__device__ __forceinline__ void mma16816(float* d, const unsigned* a, unsigned b0, unsigned b1) {
    asm volatile(
        "mma.sync.aligned.m16n8k16.row.col.f32.bf16.bf16.f32 "
        "{%0,%1,%2,%3}, {%4,%5,%6,%7}, {%8,%9}, {%0,%1,%2,%3};\n"
        : "+f"(d[0]), "+f"(d[1]), "+f"(d[2]), "+f"(d[3])
        : "r"(a[0]), "r"(a[1]), "r"(a[2]), "r"(a[3]), "r"(b0), "r"(b1));
}
__device__ __forceinline__ void ldsm4(unsigned* r, uint32_t addr) {
    asm volatile("ldmatrix.sync.aligned.m8n8.x4.shared.b16 {%0,%1,%2,%3}, [%4];\n"
        : "=r"(r[0]), "=r"(r[1]), "=r"(r[2]), "=r"(r[3]) : "r"(addr));
}
// SW128 (TMA) swizzle inside an N-row x 128B tile: granule g (16B) of row r
__device__ __forceinline__ uint32_t swoff(int row, int g) {
    return (uint32_t)(row * 128 + ((g ^ (row & 7)) << 4));
}

// ---------------------------------------------------------------------------
// bf16x3 mma.sync GEMM with TMA + mbarrier pipeline (no __syncthreads in loop).
// C[m][n] = sum_k (Ah+Al)[m][k]*(Bh+Bl)[n][k] + bias[n]   (hh + hl + lh)
// Tile 192x128, K-stage 64 (SW128), 2 stages, 160KB smem.
// 416 threads: warps 0-11 consume (3m x 4n, warp tile 64x32), warp 12 produces.
// ---------------------------------------------------------------------------
__global__ __launch_bounds__(416, 1) void k_gemm_ws(
        const __grid_constant__ CUtensorMap tAh,
        const __grid_constant__ CUtensorMap tAl,
        const __grid_constant__ CUtensorMap tBh,
        const __grid_constant__ CUtensorMap tBl,
        const float* __restrict__ bias, float* __restrict__ C,
        int Nd, unsigned long long strideC) {
    extern __shared__ __align__(16) char dsm[];
    __shared__ __align__(8) long long mbars[2 * NST];   // full[0..1], empty[0..1]

    const int tid = threadIdx.x, wid = tid >> 5, lane = tid & 31;
    const int m0 = blockIdx.y * TM, n0 = blockIdx.x * 128, bz = blockIdx.z;
    const uint32_t tile0 = (cvta_s(dsm) + 1023u) & ~1023u;
    const uint32_t mb = cvta_s(mbars);

    if (tid == 0) {
        #pragma unroll
        for (int i = 0; i < NST; i++) {
            mbar_init(mb + i * 8, 1);                 // full: 1 expect_tx arrival
            mbar_init(mb + (NST + i) * 8, NCONS);     // empty: 12 consumer warps
        }
    }
    __syncthreads();

    if (wid == NCONS) {
        // ---------------- producer ----------------
        if (lane == 0) {
            int st = 0;
            #pragma unroll 1
            for (int s = 0; s < KTILES; s++) {
                if (s >= NST) mbar_wait(mb + (NST + st) * 8, ((s / NST) - 1) & 1);
                const uint32_t base = tile0 + st * STAGEB;
                const uint32_t fb = mb + st * 8;
                mbar_expect(fb, STAGEB);
                tma3d(base,                  &tAh, s * KSTEP, m0, bz, fb);
                tma3d(base + OPA,            &tAl, s * KSTEP, m0, bz, fb);
                tma3d(base + 2 * OPA,        &tBh, s * KSTEP, n0, 0,  fb);
                tma3d(base + 2 * OPA + OPBB, &tBl, s * KSTEP, n0, 0,  fb);
                if (++st == NST) st = 0;
            }
        }
        return;
    }

    // ---------------- consumers ----------------
    const int warp_m = (wid >> 2) * 64, warp_n = (wid & 3) * 32;
    const int frow = lane & 15, fgh = lane >> 4;

    float acc[4][4][4];
    #pragma unroll
    for (int i = 0; i < 4; i++)
        #pragma unroll
        for (int j = 0; j < 4; j++)
            #pragma unroll
            for (int c = 0; c < 4; c++) acc[i][j][c] = 0.f;

    int st = 0;
    #pragma unroll 1
    for (int kt = 0; kt < KTILES; kt++) {
        mbar_wait(mb + st * 8, (kt / NST) & 1);
        const uint32_t base = tile0 + st * STAGEB;
        const uint32_t sAh = base, sAl = base + OPA;
        const uint32_t sBh = base + 2 * OPA, sBl = base + 2 * OPA + OPBB;

        #pragma unroll
        for (int k = 0; k < 4; k++) {           // four K=16 steps per stage
            const int g = 2 * k + fgh;          // granule 0..7
            unsigned ah[4][4], al[4][4];
            #pragma unroll
            for (int i = 0; i < 4; i++) {
                ldsm4(ah[i], sAh + swoff(warp_m + 16 * i + frow, g));
                ldsm4(al[i], sAl + swoff(warp_m + 16 * i + frow, g));
            }
            #pragma unroll
            for (int jb = 0; jb < 2; jb++) {    // low B-reg pressure: 8 live
                unsigned bh[4], bl[4];
                ldsm4(bh, sBh + swoff(warp_n + 16 * jb + frow, g));
                ldsm4(bl, sBl + swoff(warp_n + 16 * jb + frow, g));
                #pragma unroll
                for (int jj = 0; jj < 2; jj++) {
                    const int j = jb * 2 + jj;
                    const unsigned b0h = bh[jj], b1h = bh[2 + jj];
                    const unsigned b0l = bl[jj], b1l = bl[2 + jj];
                    #pragma unroll
                    for (int i = 0; i < 4; i++) {
                        mma16816(acc[i][j], ah[i], b0h, b1h);
                        mma16816(acc[i][j], ah[i], b0l, b1l);
                        mma16816(acc[i][j], al[i], b0h, b1h);
                    }
                }
            }
        }
        if (lane == 0) mbar_arrive(mb + (NST + st) * 8);
        if (++st == NST) st = 0;
    }

    // epilogue: +bias, fp32 stores (row-guarded: M is padded to 192*22)
    float* Cb = C + (size_t)bz * strideC + n0;
    const int fr = lane >> 2, fc2 = (lane & 3) * 2;
    #pragma unroll
    for (int i = 0; i < 4; i++)
        #pragma unroll
        for (int j = 0; j < 4; j++) {
            int r0 = m0 + warp_m + i * 16 + fr;
            int c0 = warp_n + j * 8 + fc2;
            float2 bv = *(const float2*)&bias[n0 + c0];
            if (r0 < NHW)
                *(float2*)&Cb[(size_t)r0 * Nd + c0] =
                    make_float2(acc[i][j][0] + bv.x, acc[i][j][1] + bv.y);
            if (r0 + 8 < NHW)
                *(float2*)&Cb[(size_t)(r0 + 8) * Nd + c0] =
                    make_float2(acc[i][j][2] + bv.x, acc[i][j][3] + bv.y);
        }
}

// ---------------------------------------------------------------------------
// Transpose [K][N] fp32 -> [N][K] bf16 hi/lo.
// ---------------------------------------------------------------------------
__global__ void k_tsplit(const float* __restrict__ src,
                         __nv_bfloat16* __restrict__ dh,
                         __nv_bfloat16* __restrict__ dl,
                         int K, int N) {
    __shared__ float t[32][33];
    const int n0 = blockIdx.x * 32, k0 = blockIdx.y * 32;
    src += (size_t)blockIdx.z * K * N;
    dh  += (size_t)blockIdx.z * N * K;
    dl  += (size_t)blockIdx.z * N * K;
    const int tx = threadIdx.x, ty = threadIdx.y;
    #pragma unroll
    for (int r = 0; r < 4; r++)
        t[ty + r * 8][tx] = src[(size_t)(k0 + ty + r * 8) * N + n0 + tx];
    __syncthreads();
    #pragma unroll
    for (int r = 0; r < 4; r++) {
        float v = t[tx][ty + r * 8];
        __nv_bfloat16 h = __float2bfloat16(v);
        __nv_bfloat16 l = __float2bfloat16(v - __bfloat162float(h));
        size_t o = (size_t)(n0 + ty + r * 8) * K + k0 + tx;
        dh[o] = h;
        dl[o] = l;
    }
}

// ---------------------------------------------------------------------------
// Normalize q,k per token; accumulate masked/unmasked k*v partial sums.
// ---------------------------------------------------------------------------
__global__ __launch_bounds__(256) void k_normred(const float* __restrict__ mask) {
    const int b     = blockIdx.x >> 7;
    const int chunk = blockIdx.x & 127;
    const int warp  = threadIdx.x >> 5, lane = threadIdx.x & 31;

    float accK[16], accM[16];
    #pragma unroll
    for (int i = 0; i < 16; i++) { accK[i] = 0.f; accM[i] = 0.f; }

    #pragma unroll 1
    for (int it = 0; it < 4; it++) {
        const int t = chunk * 32 + warp * 4 + it;
        float* row = g_qkv + ((size_t)b * NHW + t) * NQKV;
        float q[16], kk[16], vv[16];
        float qss = 0.f, kss = 0.f;
        #pragma unroll
        for (int r = 0; r < 4; r++) {
            int c = (lane + 32 * r) * 4;
            float4 qa = *(const float4*)&row[c];
            float4 ka = *(const float4*)&row[512 + c];
            float4 va = *(const float4*)&row[1024 + c];
            q[r*4+0]=qa.x; q[r*4+1]=qa.y; q[r*4+2]=qa.z; q[r*4+3]=qa.w;
            kk[r*4+0]=ka.x; kk[r*4+1]=ka.y; kk[r*4+2]=ka.z; kk[r*4+3]=ka.w;
            vv[r*4+0]=va.x; vv[r*4+1]=va.y; vv[r*4+2]=va.z; vv[r*4+3]=va.w;
            qss += qa.x*qa.x + qa.y*qa.y + qa.z*qa.z + qa.w*qa.w;
            kss += ka.x*ka.x + ka.y*ka.y + ka.z*ka.z + ka.w*ka.w;
        }
        #pragma unroll
        for (int off = 16; off > 0; off >>= 1) {
            qss += __shfl_xor_sync(0xffffffffu, qss, off);
            kss += __shfl_xor_sync(0xffffffffu, kss, off);
        }
        const float rq = rsqrtf(qss), rk = rsqrtf(kss);
        const bool sel = mask[b * NHW + t] > 0.5f;
        #pragma unroll
        for (int i = 0; i < 16; i++) {
            float qn = q[i] * rq;
            q[i] = qn;
            float con = kk[i] * rk * vv[i];
            if (sel) accM[i] += con; else accK[i] += con;
        }
        #pragma unroll
        for (int r = 0; r < 4; r++) {
            int c = (lane + 32 * r) * 4;
            *(float4*)&row[c] = make_float4(q[r*4], q[r*4+1], q[r*4+2], q[r*4+3]);
        }
    }

    __shared__ float sh[8][1024];
    #pragma unroll
    for (int r = 0; r < 4; r++) {
        int c = (lane + 32 * r) * 4;
        *(float4*)&sh[warp][c]       = make_float4(accK[r*4], accK[r*4+1], accK[r*4+2], accK[r*4+3]);
        *(float4*)&sh[warp][512 + c] = make_float4(accM[r*4], accM[r*4+1], accM[r*4+2], accM[r*4+3]);
    }
    __syncthreads();
    float* part = g_part + (size_t)blockIdx.x * 1024;
    #pragma unroll
    for (int i = 0; i < 4; i++) {
        int ch = threadIdx.x + 256 * i;
        float s = 0.f;
        #pragma unroll
        for (int w = 0; w < 8; w++) s += sh[w][ch];
        part[ch] = s;
    }
}

__global__ void k_reduce_s() {
    const int idx = blockIdx.x * 256 + threadIdx.x;
    const int ch = idx & 1023;
    const int b = idx >> 10;
    float s = 0.f;
    for (int c2 = 0; c2 < 128; c2++)
        s += g_part[((size_t)(b * 128 + c2)) * 1024 + ch];
    if (ch >= 512) s *= 0.7f;
    g_s[idx] = s;
}

__global__ void k_scaleq(const float* __restrict__ mask) {
    const size_t idx = ((size_t)blockIdx.x * 256 + threadIdx.x) * 4;
    const int bt = (int)(idx >> 9);
    const int c  = (int)(idx & 511);
    const float4 q = *(const float4*)&g_qkv[(size_t)bt * NQKV + c];
    const bool sel = mask[bt] > 0.5f;
    const float4 sv = *(const float4*)&g_s[(bt >> 12) * 1024 + (sel ? 512 : 0) + c];
    float v[4] = {q.x * sv.x, q.y * sv.y, q.z * sv.z, q.w * sv.w};
    union { __nv_bfloat16 b[4]; uint2 u; } H, L;
    #pragma unroll
    for (int i = 0; i < 4; i++) {
        H.b[i] = __float2bfloat16(v[i]);
        L.b[i] = __float2bfloat16(v[i] - __bfloat162float(H.b[i]));
    }
    *(uint2*)&g_qah[idx] = H.u;
    *(uint2*)&g_qal[idx] = L.u;
}

// ---------------------------------------------------------------------------
// Host: tensormap construction via driver entry point (no -lcuda link needed)
// ---------------------------------------------------------------------------
typedef CUresult (CUDAAPI *PFN_encode)(
    CUtensorMap*, CUtensorMapDataType, cuuint32_t, void*,
    const cuuint64_t*, const cuuint64_t*, const cuuint32_t*, const cuuint32_t*,
    CUtensorMapInterleave, CUtensorMapSwizzle, CUtensorMapL2promotion,
    CUtensorMapFloatOOBfill);

static PFN_encode get_encoder() {
    static PFN_encode fn = nullptr;
    if (!fn) {
        void* p = nullptr;
        cudaDriverEntryPointQueryResult qr;
        cudaGetDriverEntryPointByVersion("cuTensorMapEncodeTiled", &p, 12000,
                                         cudaEnableDefault, &qr);
        fn = (PFN_encode)p;
    }
    return fn;
}

static void build_map(CUtensorMap* m, const void* ptr,
                      unsigned long long d1, unsigned long long d2,
                      unsigned box_rows) {
    cuuint64_t dims[3] = {NC, d1, d2};
    cuuint64_t st[2]   = {NC * 2ull, d1 * NC * 2ull};
    cuuint32_t box[3]  = {KSTEP, box_rows, 1};   // 64 bf16 = 128B rows (SW128)
    cuuint32_t es[3]   = {1, 1, 1};
    get_encoder()(m, CU_TENSOR_MAP_DATA_TYPE_BFLOAT16, 3, (void*)ptr,
                  dims, st, box, es,
                  CU_TENSOR_MAP_INTERLEAVE_NONE, CU_TENSOR_MAP_SWIZZLE_128B,
                  CU_TENSOR_MAP_L2_PROMOTION_L2_128B,
                  CU_TENSOR_MAP_FLOAT_OOB_FILL_NONE);
}

extern "C" void kernel_launch(void* const* d_in, const int* in_sizes, int n_in,
                              void* d_out, int out_size) {
    const float* x    = (const float*)d_in[0];
    const float* mask = (const float*)d_in[1];
    const float* Wq   = (const float*)d_in[2];
    const float* bq   = (const float*)d_in[3];
    const float* Wo   = (const float*)d_in[4];
    const float* bo   = (const float*)d_in[5];
    float* out = (float*)d_out;

    __nv_bfloat16 *xh, *xl, *wqh, *wql, *woh, *wol, *qah, *qal;
    float* qkvp;
    cudaGetSymbolAddress((void**)&xh,  g_xh);
    cudaGetSymbolAddress((void**)&xl,  g_xl);
    cudaGetSymbolAddress((void**)&wqh, g_wqh);
    cudaGetSymbolAddress((void**)&wql, g_wql);
    cudaGetSymbolAddress((void**)&woh, g_woh);
    cudaGetSymbolAddress((void**)&wol, g_wol);
    cudaGetSymbolAddress((void**)&qah, g_qah);
    cudaGetSymbolAddress((void**)&qal, g_qal);
    cudaGetSymbolAddress((void**)&qkvp, g_qkv);

    CUtensorMap mXh, mXl, mWqh, mWql, mQh, mQl, mWoh, mWol;
    build_map(&mXh,  xh,  NHW,  NB, TM);    // A tiles: 192 rows
    build_map(&mXl,  xl,  NHW,  NB, TM);
    build_map(&mQh,  qah, NHW,  NB, TM);
    build_map(&mQl,  qal, NHW,  NB, TM);
    build_map(&mWqh, wqh, NQKV, 1, 128);    // B tiles: 128 rows
    build_map(&mWql, wql, NQKV, 1, 128);
    build_map(&mWoh, woh, NC,   1, 128);
    build_map(&mWol, wol, NC,   1, 128);

    cudaFuncSetAttribute(k_gemm_ws,
                         cudaFuncAttributeMaxDynamicSharedMemorySize, DSMEM);

    k_tsplit<<<dim3(NHW / 32, NC / 32, NB), dim3(32, 8)>>>(x, xh, xl, NC, NHW);
    k_tsplit<<<dim3(NQKV / 32, NC / 32, 1), dim3(32, 8)>>>(Wq, wqh, wql, NC, NQKV);
    k_tsplit<<<dim3(NC / 32, NC / 32, 1), dim3(32, 8)>>>(Wo, woh, wol, NC, NC);

    // GEMM1: qkv = x^T @ Wqkv + bq   (M=4096/b padded to 4224, N=1536, K=512)
    k_gemm_ws<<<dim3(NQKV / 128, MTILES, NB), 416, DSMEM>>>(
        mXh, mXl, mWqh, mWql, bq, qkvp, NQKV, (unsigned long long)NHW * NQKV);

    k_normred<<<NB * 128, 256>>>(mask);
    k_reduce_s<<<32, 256>>>();
    k_scaleq<<<(NB * NHW * NC) / 1024, 256>>>(mask);

    // GEMM2: out = qA @ Wout + bo   (M=4096/b padded, N=512, K=512)
    k_gemm_ws<<<dim3(NC / 128, MTILES, NB), 416, DSMEM>>>(
        mQh, mQl, mWoh, mWol, bo, out, NC, (unsigned long long)NHW * NC);
}

// round 12
// speedup vs baseline: 1.2517x; 1.2517x over previous
#include <cuda_runtime.h>
#include <cuda.h>
#include <cuda_fp16.h>
#include <cstdint>

#define NB   8
#define NC   512
#define NHW  4096
#define NQKV 1536

#define KSTEP   64                      // K elems per stage = 128B rows (SW128)
#define KTILES  (NC / KSTEP)            // 8
#define TM      192                     // M tile rows (3 warp rows of 64)
#define MTILES  ((NHW + TM - 1) / TM)   // 22 (padded; TMA zero-fills OOB)
#define OPA     (TM * 128)              // A operand tile: 192 rows x 128B = 24KB
#define OPBB    (128 * 128)             // B operand tile: 128 rows x 128B = 16KB
#define STAGEB  (2 * OPA + OPBB)        // Ah, Al, B = 64KB
#define NST     3
#define DSMEM   (NST * STAGEB + 1024)   // 192KB + align slack
#define NCONS   12                      // consumer warps (3m x 4n)

// ---------------- scratch (__device__ globals; no allocs allowed) ----------------
__device__ float g_qkv[(size_t)NB * NHW * NQKV];
__device__ float g_part[NB * 128 * 1024];
__device__ float g_s[NB * 1024];

__device__ __align__(16) __half g_xh[(size_t)NB * NHW * NC];   // x^T hi  [b][t][c]
__device__ __align__(16) __half g_xl[(size_t)NB * NHW * NC];   // x^T lo
__device__ __align__(16) __half g_wq[(size_t)NQKV * NC];       // Wqkv^T fp16 [j][c]
__device__ __align__(16) __half g_wo[(size_t)NC * NC];         // Wout^T fp16 [j][c]
__device__ __align__(16) __half g_qah[(size_t)NB * NHW * NC];  // scaled qn hi
__device__ __align__(16) __half g_qal[(size_t)NB * NHW * NC];  // scaled qn lo

// ---------------------------------------------------------------------------
// PTX helpers (TMA / mbarrier / mma / ldmatrix)
// ---------------------------------------------------------------------------
__device__ __forceinline__ uint32_t cvta_s(const void* p) {
    return (uint32_t)__cvta_generic_to_shared(p);
}
__device__ __forceinline__ void mbar_init(uint32_t a, uint32_t c) {
    asm volatile("mbarrier.init.shared.b64 [%0], %1;" :: "r"(a), "r"(c) : "memory");
}
__device__ __forceinline__ void mbar_expect(uint32_t a, uint32_t tx) {
    asm volatile("mbarrier.arrive.expect_tx.shared.b64 _, [%0], %1;" :: "r"(a), "r"(tx) : "memory");
}
__device__ __forceinline__ void mbar_arrive(uint32_t a) {
    asm volatile("mbarrier.arrive.shared.b64 _, [%0];" :: "r"(a) : "memory");
}
__device__ __forceinline__ void mbar_wait(uint32_t a, uint32_t ph) {
    asm volatile(
        "{\n\t.reg .pred P;\n"
        "W%=:\n\tmbarrier.try_wait.parity.shared.b64 P, [%0], %1, 0x989680;\n"
        "\t@P bra D%=;\n\tbra W%=;\nD%=:\n\t}"
        :: "r"(a), "r"(ph) : "memory");
}
__device__ __forceinline__ void tma3d(uint32_t sa, const CUtensorMap* tm,
                                      int cx, int cy, int cz, uint32_t mb) {
    asm volatile(
        "cp.async.bulk.tensor.3d.shared::cta.global.tile.mbarrier::complete_tx::bytes "
        "[%0], [%1, {%2, %3, %4}], [%5];"
        :: "r"(sa), "l"(tm), "r"(cx), "r"(cy), "r"(cz), "r"(mb) : "memory");
}
__device__ __forceinline__ void mma16816(float* d, const unsigned* a, unsigned b0, unsigned b1) {
    asm volatile(
        "mma.sync.aligned.m16n8k16.row.col.f32.f16.f16.f32 "
        "{%0,%1,%2,%3}, {%4,%5,%6,%7}, {%8,%9}, {%0,%1,%2,%3};\n"
        : "+f"(d[0]), "+f"(d[1]), "+f"(d[2]), "+f"(d[3])
        : "r"(a[0]), "r"(a[1]), "r"(a[2]), "r"(a[3]), "r"(b0), "r"(b1));
}
__device__ __forceinline__ void ldsm4(unsigned* r, uint32_t addr) {
    asm volatile("ldmatrix.sync.aligned.m8n8.x4.shared.b16 {%0,%1,%2,%3}, [%4];\n"
        : "=r"(r[0]), "=r"(r[1]), "=r"(r[2]), "=r"(r[3]) : "r"(addr));
}
// SW128 row-base offset with g=0: row*128 + ((row&7)<<4).
// Full addr for granule g is (base + rowoff) ^ (g<<4)  (bases are 1024-aligned).
__device__ __forceinline__ uint32_t rowoff0(int row) {
    return (uint32_t)(row * 128 + ((row & 7) << 4));
}

// ---------------------------------------------------------------------------
// fp16 2-term mma.sync GEMM with TMA + mbarrier pipeline.
// C[m][n] = sum_k (Ah+Al)[m][k]*B[n][k] + bias[n]
// Tile 192x128, K-stage 64 (SW128), 3 stages, 192KB smem.
// 416 threads: warps 0-11 consume (3m x 4n, warp tile 64x32), warp 12 produces.
// ---------------------------------------------------------------------------
__global__ __launch_bounds__(416, 1) void k_gemm_ws(
        const __grid_constant__ CUtensorMap tAh,
        const __grid_constant__ CUtensorMap tAl,
        const __grid_constant__ CUtensorMap tB,
        const float* __restrict__ bias, float* __restrict__ C,
        int Nd, unsigned long long strideC) {
    extern __shared__ __align__(16) char dsm[];
    __shared__ __align__(8) long long mbars[2 * NST];   // full[0..2], empty[0..2]

    const int tid = threadIdx.x, wid = tid >> 5, lane = tid & 31;
    const int m0 = blockIdx.y * TM, n0 = blockIdx.x * 128, bz = blockIdx.z;
    const uint32_t tile0 = (cvta_s(dsm) + 1023u) & ~1023u;
    const uint32_t mb = cvta_s(mbars);

    if (tid == 0) {
        #pragma unroll
        for (int i = 0; i < NST; i++) {
            mbar_init(mb + i * 8, 1);                 // full: 1 expect_tx arrival
            mbar_init(mb + (NST + i) * 8, NCONS);     // empty: 12 consumer warps
        }
    }
    __syncthreads();

    if (wid == NCONS) {
        // ---------------- producer ----------------
        if (lane == 0) {
            int st = 0;
            #pragma unroll 1
            for (int s = 0; s < KTILES; s++) {
                if (s >= NST) mbar_wait(mb + (NST + st) * 8, ((s / NST) - 1) & 1);
                const uint32_t base = tile0 + st * STAGEB;
                const uint32_t fb = mb + st * 8;
                mbar_expect(fb, STAGEB);
                tma3d(base,           &tAh, s * KSTEP, m0, bz, fb);
                tma3d(base + OPA,     &tAl, s * KSTEP, m0, bz, fb);
                tma3d(base + 2 * OPA, &tB,  s * KSTEP, n0, 0,  fb);
                if (++st == NST) st = 0;
            }
        }
        return;
    }

    // ---------------- consumers ----------------
    const int warp_m = (wid >> 2) * 64, warp_n = (wid & 3) * 32;
    const int frow = lane & 15, fgh = lane >> 4;

    // per-warp row-base offsets (stage-independent)
    uint32_t roA[4], roB[2];
    #pragma unroll
    for (int i = 0; i < 4; i++) roA[i] = rowoff0(warp_m + 16 * i + frow);
    #pragma unroll
    for (int jb = 0; jb < 2; jb++) roB[jb] = rowoff0(warp_n + 16 * jb + frow);

    float acc[4][4][4];
    #pragma unroll
    for (int i = 0; i < 4; i++)
        #pragma unroll
        for (int j = 0; j < 4; j++)
            #pragma unroll
            for (int c = 0; c < 4; c++) acc[i][j][c] = 0.f;

    int st = 0;
    #pragma unroll 1
    for (int kt = 0; kt < KTILES; kt++) {
        mbar_wait(mb + st * 8, (kt / NST) & 1);
        const uint32_t base = tile0 + st * STAGEB;
        const uint32_t sAh = base, sAl = base + OPA, sB = base + 2 * OPA;

        #pragma unroll
        for (int k = 0; k < 4; k++) {           // four K=16 steps per stage
            const uint32_t gsh = (uint32_t)((2 * k + fgh) << 4);
            unsigned ah[4][4], al[4][4];
            #pragma unroll
            for (int i = 0; i < 4; i++) {
                ldsm4(ah[i], (sAh + roA[i]) ^ gsh);
                ldsm4(al[i], (sAl + roA[i]) ^ gsh);
            }
            #pragma unroll
            for (int jb = 0; jb < 2; jb++) {
                unsigned bf[4];
                ldsm4(bf, (sB + roB[jb]) ^ gsh);
                // term-outer ordering: adjacent MMAs hit distinct accumulators
                #pragma unroll
                for (int t = 0; t < 2; t++)
                    #pragma unroll
                    for (int jj = 0; jj < 2; jj++) {
                        const int j = jb * 2 + jj;
                        const unsigned b0 = bf[jj], b1 = bf[2 + jj];
                        #pragma unroll
                        for (int i = 0; i < 4; i++)
                            mma16816(acc[i][j], t ? al[i] : ah[i], b0, b1);
                    }
            }
        }
        if (lane == 0) mbar_arrive(mb + (NST + st) * 8);
        if (++st == NST) st = 0;
    }

    // epilogue: +bias, fp32 stores (row-guarded: M padded to 192*22)
    float* Cb = C + (size_t)bz * strideC + n0;
    const int fr = lane >> 2, fc2 = (lane & 3) * 2;
    #pragma unroll
    for (int i = 0; i < 4; i++)
        #pragma unroll
        for (int j = 0; j < 4; j++) {
            int r0 = m0 + warp_m + i * 16 + fr;
            int c0 = warp_n + j * 8 + fc2;
            float2 bv = *(const float2*)&bias[n0 + c0];
            if (r0 < NHW)
                *(float2*)&Cb[(size_t)r0 * Nd + c0] =
                    make_float2(acc[i][j][0] + bv.x, acc[i][j][1] + bv.y);
            if (r0 + 8 < NHW)
                *(float2*)&Cb[(size_t)(r0 + 8) * Nd + c0] =
                    make_float2(acc[i][j][2] + bv.x, acc[i][j][3] + bv.y);
        }
}

// ---------------------------------------------------------------------------
// Transpose [K][N] fp32 -> [N][K] fp16 hi/lo split.
// ---------------------------------------------------------------------------
__global__ void k_tsplit(const float* __restrict__ src,
                         __half* __restrict__ dh, __half* __restrict__ dl,
                         int K, int N) {
    __shared__ float t[32][33];
    const int n0 = blockIdx.x * 32, k0 = blockIdx.y * 32;
    src += (size_t)blockIdx.z * K * N;
    dh  += (size_t)blockIdx.z * N * K;
    dl  += (size_t)blockIdx.z * N * K;
    const int tx = threadIdx.x, ty = threadIdx.y;
    #pragma unroll
    for (int r = 0; r < 4; r++)
        t[ty + r * 8][tx] = src[(size_t)(k0 + ty + r * 8) * N + n0 + tx];
    __syncthreads();
    #pragma unroll
    for (int r = 0; r < 4; r++) {
        float v = t[tx][ty + r * 8];
        __half h = __float2half_rn(v);
        __half l = __float2half_rn(v - __half2float(h));
        size_t o = (size_t)(n0 + ty + r * 8) * K + k0 + tx;
        dh[o] = h;
        dl[o] = l;
    }
}

// Transpose [K][N] fp32 -> [N][K] single fp16 (weights).
__global__ void k_tsingle(const float* __restrict__ src,
                          __half* __restrict__ dh, int K, int N) {
    __shared__ float t[32][33];
    const int n0 = blockIdx.x * 32, k0 = blockIdx.y * 32;
    const int tx = threadIdx.x, ty = threadIdx.y;
    #pragma unroll
    for (int r = 0; r < 4; r++)
        t[ty + r * 8][tx] = src[(size_t)(k0 + ty + r * 8) * N + n0 + tx];
    __syncthreads();
    #pragma unroll
    for (int r = 0; r < 4; r++)
        dh[(size_t)(n0 + ty + r * 8) * K + k0 + tx] = __float2half_rn(t[tx][ty + r * 8]);
}

// ---------------------------------------------------------------------------
// Normalize q,k per token; accumulate masked/unmasked k*v partial sums.
// ---------------------------------------------------------------------------
__global__ __launch_bounds__(256) void k_normred(const float* __restrict__ mask) {
    const int b     = blockIdx.x >> 7;
    const int chunk = blockIdx.x & 127;
    const int warp  = threadIdx.x >> 5, lane = threadIdx.x & 31;

    float accK[16], accM[16];
    #pragma unroll
    for (int i = 0; i < 16; i++) { accK[i] = 0.f; accM[i] = 0.f; }

    #pragma unroll 1
    for (int it = 0; it < 4; it++) {
        const int t = chunk * 32 + warp * 4 + it;
        float* row = g_qkv + ((size_t)b * NHW + t) * NQKV;
        float q[16], kk[16], vv[16];
        float qss = 0.f, kss = 0.f;
        #pragma unroll
        for (int r = 0; r < 4; r++) {
            int c = (lane + 32 * r) * 4;
            float4 qa = *(const float4*)&row[c];
            float4 ka = *(const float4*)&row[512 + c];
            float4 va = *(const float4*)&row[1024 + c];
            q[r*4+0]=qa.x; q[r*4+1]=qa.y; q[r*4+2]=qa.z; q[r*4+3]=qa.w;
            kk[r*4+0]=ka.x; kk[r*4+1]=ka.y; kk[r*4+2]=ka.z; kk[r*4+3]=ka.w;
            vv[r*4+0]=va.x; vv[r*4+1]=va.y; vv[r*4+2]=va.z; vv[r*4+3]=va.w;
            qss += qa.x*qa.x + qa.y*qa.y + qa.z*qa.z + qa.w*qa.w;
            kss += ka.x*ka.x + ka.y*ka.y + ka.z*ka.z + ka.w*ka.w;
        }
        #pragma unroll
        for (int off = 16; off > 0; off >>= 1) {
            qss += __shfl_xor_sync(0xffffffffu, qss, off);
            kss += __shfl_xor_sync(0xffffffffu, kss, off);
        }
        const float rq = rsqrtf(qss), rk = rsqrtf(kss);
        const bool sel = mask[b * NHW + t] > 0.5f;
        #pragma unroll
        for (int i = 0; i < 16; i++) {
            float qn = q[i] * rq;
            q[i] = qn;
            float con = kk[i] * rk * vv[i];
            if (sel) accM[i] += con; else accK[i] += con;
        }
        #pragma unroll
        for (int r = 0; r < 4; r++) {
            int c = (lane + 32 * r) * 4;
            *(float4*)&row[c] = make_float4(q[r*4], q[r*4+1], q[r*4+2], q[r*4+3]);
        }
    }

    __shared__ float sh[8][1024];
    #pragma unroll
    for (int r = 0; r < 4; r++) {
        int c = (lane + 32 * r) * 4;
        *(float4*)&sh[warp][c]       = make_float4(accK[r*4], accK[r*4+1], accK[r*4+2], accK[r*4+3]);
        *(float4*)&sh[warp][512 + c] = make_float4(accM[r*4], accM[r*4+1], accM[r*4+2], accM[r*4+3]);
    }
    __syncthreads();
    float* part = g_part + (size_t)blockIdx.x * 1024;
    #pragma unroll
    for (int i = 0; i < 4; i++) {
        int ch = threadIdx.x + 256 * i;
        float s = 0.f;
        #pragma unroll
        for (int w = 0; w < 8; w++) s += sh[w][ch];
        part[ch] = s;
    }
}

__global__ void k_reduce_s() {
    const int idx = blockIdx.x * 256 + threadIdx.x;
    const int ch = idx & 1023;
    const int b = idx >> 10;
    float s = 0.f;
    for (int c2 = 0; c2 < 128; c2++)
        s += g_part[((size_t)(b * 128 + c2)) * 1024 + ch];
    if (ch >= 512) s *= 0.7f;
    g_s[idx] = s;
}

__global__ void k_scaleq(const float* __restrict__ mask) {
    const size_t idx = ((size_t)blockIdx.x * 256 + threadIdx.x) * 4;
    const int bt = (int)(idx >> 9);
    const int c  = (int)(idx & 511);
    const float4 q = *(const float4*)&g_qkv[(size_t)bt * NQKV + c];
    const bool sel = mask[bt] > 0.5f;
    const float4 sv = *(const float4*)&g_s[(bt >> 12) * 1024 + (sel ? 512 : 0) + c];
    float v[4] = {q.x * sv.x, q.y * sv.y, q.z * sv.z, q.w * sv.w};
    union { __half h[4]; uint2 u; } H, L;
    #pragma unroll
    for (int i = 0; i < 4; i++) {
        H.h[i] = __float2half_rn(v[i]);
        L.h[i] = __float2half_rn(v[i] - __half2float(H.h[i]));
    }
    *(uint2*)&g_qah[idx] = H.u;
    *(uint2*)&g_qal[idx] = L.u;
}

// ---------------------------------------------------------------------------
// Host: tensormap construction via driver entry point (no -lcuda link needed)
// ---------------------------------------------------------------------------
typedef CUresult (CUDAAPI *PFN_encode)(
    CUtensorMap*, CUtensorMapDataType, cuuint32_t, void*,
    const cuuint64_t*, const cuuint64_t*, const cuuint32_t*, const cuuint32_t*,
    CUtensorMapInterleave, CUtensorMapSwizzle, CUtensorMapL2promotion,
    CUtensorMapFloatOOBfill);

static PFN_encode get_encoder() {
    static PFN_encode fn = nullptr;
    if (!fn) {
        void* p = nullptr;
        cudaDriverEntryPointQueryResult qr;
        cudaGetDriverEntryPointByVersion("cuTensorMapEncodeTiled", &p, 12000,
                                         cudaEnableDefault, &qr);
        fn = (PFN_encode)p;
    }
    return fn;
}

static void build_map(CUtensorMap* m, const void* ptr,
                      unsigned long long d1, unsigned long long d2,
                      unsigned box_rows) {
    cuuint64_t dims[3] = {NC, d1, d2};
    cuuint64_t st[2]   = {NC * 2ull, d1 * NC * 2ull};
    cuuint32_t box[3]  = {KSTEP, box_rows, 1};   // 64 fp16 = 128B rows (SW128)
    cuuint32_t es[3]   = {1, 1, 1};
    get_encoder()(m, CU_TENSOR_MAP_DATA_TYPE_FLOAT16, 3, (void*)ptr,
                  dims, st, box, es,
                  CU_TENSOR_MAP_INTERLEAVE_NONE, CU_TENSOR_MAP_SWIZZLE_128B,
                  CU_TENSOR_MAP_L2_PROMOTION_L2_128B,
                  CU_TENSOR_MAP_FLOAT_OOB_FILL_NONE);
}

extern "C" void kernel_launch(void* const* d_in, const int* in_sizes, int n_in,
                              void* d_out, int out_size) {
    const float* x    = (const float*)d_in[0];
    const float* mask = (const float*)d_in[1];
    const float* Wq   = (const float*)d_in[2];
    const float* bq   = (const float*)d_in[3];
    const float* Wo   = (const float*)d_in[4];
    const float* bo   = (const float*)d_in[5];
    float* out = (float*)d_out;

    __half *xh, *xl, *wq, *wo, *qah, *qal;
    float* qkvp;
    cudaGetSymbolAddress((void**)&xh,  g_xh);
    cudaGetSymbolAddress((void**)&xl,  g_xl);
    cudaGetSymbolAddress((void**)&wq,  g_wq);
    cudaGetSymbolAddress((void**)&wo,  g_wo);
    cudaGetSymbolAddress((void**)&qah, g_qah);
    cudaGetSymbolAddress((void**)&qal, g_qal);
    cudaGetSymbolAddress((void**)&qkvp, g_qkv);

    CUtensorMap mXh, mXl, mWq, mQh, mQl, mWo;
    build_map(&mXh, xh,  NHW,  NB, TM);    // A tiles: 192 rows
    build_map(&mXl, xl,  NHW,  NB, TM);
    build_map(&mQh, qah, NHW,  NB, TM);
    build_map(&mQl, qal, NHW,  NB, TM);
    build_map(&mWq, wq,  NQKV, 1, 128);    // B tiles: 128 rows
    build_map(&mWo, wo,  NC,   1, 128);

    cudaFuncSetAttribute(k_gemm_ws,
                         cudaFuncAttributeMaxDynamicSharedMemorySize, DSMEM);

    k_tsplit<<<dim3(NHW / 32, NC / 32, NB), dim3(32, 8)>>>(x, xh, xl, NC, NHW);
    k_tsingle<<<dim3(NQKV / 32, NC / 32, 1), dim3(32, 8)>>>(Wq, wq, NC, NQKV);
    k_tsingle<<<dim3(NC / 32, NC / 32, 1), dim3(32, 8)>>>(Wo, wo, NC, NC);

    // GEMM1: qkv = x^T @ Wqkv + bq   (M=4096/b padded to 4224, N=1536, K=512)
    k_gemm_ws<<<dim3(NQKV / 128, MTILES, NB), 416, DSMEM>>>(
        mXh, mXl, mWq, bq, qkvp, NQKV, (unsigned long long)NHW * NQKV);

    k_normred<<<NB * 128, 256>>>(mask);
    k_reduce_s<<<32, 256>>>();
    k_scaleq<<<(NB * NHW * NC) / 1024, 256>>>(mask);

    // GEMM2: out = qA @ Wout + bo   (M=4096/b padded, N=512, K=512)
    k_gemm_ws<<<dim3(NC / 128, MTILES, NB), 416, DSMEM>>>(
        mQh, mQl, mWo, bo, out, NC, (unsigned long long)NHW * NC);
}

// round 14
// speedup vs baseline: 1.3583x; 1.0851x over previous
#include <cuda_runtime.h>
#include <cuda.h>
#include <cuda_fp16.h>
#include <cstdint>

#define NB   8
#define NC   512
#define NHW  4096
#define NQKV 1536

#define KSTEP   64                      // K elems per stage = 128B rows (SW128)
#define KTILES  (NC / KSTEP)            // 8
#define TM      192                     // M tile rows (3 warp rows of 64)
#define MTILES  ((NHW + TM - 1) / TM)   // 22 (padded; TMA zero-fills OOB)
#define OPA     (TM * 128)              // A operand tile: 192 rows x 128B = 24KB
#define OPBB    (128 * 128)             // B operand tile: 128 rows x 128B = 16KB
#define NST     3
#define NCONS   12                      // consumer warps (3m x 4n)

// ---------------- scratch (__device__ globals; no allocs allowed) ----------------
__device__ float g_qkv[(size_t)NB * NHW * NQKV];
__device__ float g_part[NB * 128 * 1024];
__device__ float g_s[NB * 1024];

__device__ __align__(16) __half g_xh[(size_t)NB * NHW * NC];   // x^T hi  [b][t][c]
__device__ __align__(16) __half g_xl[(size_t)NB * NHW * NC];   // x^T lo
__device__ __align__(16) __half g_wq[(size_t)NQKV * NC];       // Wqkv^T fp16 [j][c]
__device__ __align__(16) __half g_wo[(size_t)NC * NC];         // Wout^T fp16 [j][c]
__device__ __align__(16) __half g_qah[(size_t)NB * NHW * NC];  // scaled qn fp16

// ---------------------------------------------------------------------------
// PTX helpers (TMA / mbarrier / mma / ldmatrix)
// ---------------------------------------------------------------------------
__device__ __forceinline__ uint32_t cvta_s(const void* p) {
    return (uint32_t)__cvta_generic_to_shared(p);
}
__device__ __forceinline__ void mbar_init(uint32_t a, uint32_t c) {
    asm volatile("mbarrier.init.shared.b64 [%0], %1;" :: "r"(a), "r"(c) : "memory");
}
__device__ __forceinline__ void mbar_expect(uint32_t a, uint32_t tx) {
    asm volatile("mbarrier.arrive.expect_tx.shared.b64 _, [%0], %1;" :: "r"(a), "r"(tx) : "memory");
}
__device__ __forceinline__ void mbar_arrive(uint32_t a) {
    asm volatile("mbarrier.arrive.shared.b64 _, [%0];" :: "r"(a) : "memory");
}
__device__ __forceinline__ void mbar_wait(uint32_t a, uint32_t ph) {
    asm volatile(
        "{\n\t.reg .pred P;\n"
        "W%=:\n\tmbarrier.try_wait.parity.shared.b64 P, [%0], %1, 0x989680;\n"
        "\t@P bra D%=;\n\tbra W%=;\nD%=:\n\t}"
        :: "r"(a), "r"(ph) : "memory");
}
__device__ __forceinline__ void tma3d(uint32_t sa, const CUtensorMap* tm,
                                      int cx, int cy, int cz, uint32_t mb) {
    asm volatile(
        "cp.async.bulk.tensor.3d.shared::cta.global.tile.mbarrier::complete_tx::bytes "
        "[%0], [%1, {%2, %3, %4}], [%5];"
        :: "r"(sa), "l"(tm), "r"(cx), "r"(cy), "r"(cz), "r"(mb) : "memory");
}
__device__ __forceinline__ void mma16816(float* d, const unsigned* a, unsigned b0, unsigned b1) {
    asm volatile(
        "mma.sync.aligned.m16n8k16.row.col.f32.f16.f16.f32 "
        "{%0,%1,%2,%3}, {%4,%5,%6,%7}, {%8,%9}, {%0,%1,%2,%3};\n"
        : "+f"(d[0]), "+f"(d[1]), "+f"(d[2]), "+f"(d[3])
        : "r"(a[0]), "r"(a[1]), "r"(a[2]), "r"(a[3]), "r"(b0), "r"(b1));
}
__device__ __forceinline__ void ldsm4(unsigned* r, uint32_t addr) {
    asm volatile("ldmatrix.sync.aligned.m8n8.x4.shared.b16 {%0,%1,%2,%3}, [%4];\n"
        : "=r"(r[0]), "=r"(r[1]), "=r"(r[2]), "=r"(r[3]) : "r"(addr));
}
// SW128 row-base offset with g=0: row*128 + ((row&7)<<4).
// Full addr for granule g is (base + rowoff) ^ (g<<4)  (bases are 1024-aligned).
__device__ __forceinline__ uint32_t rowoff0(int row) {
    return (uint32_t)(row * 128 + ((row & 7) << 4));
}

// ---------------------------------------------------------------------------
// fp16 mma.sync GEMM with TMA + mbarrier pipeline.
// TERMS=2: C = (Ah+Al)·B^T + bias    TERMS=1: C = Ah·B^T + bias
// Tile 192x128, K-stage 64 (SW128), 3 stages.
// 416 threads: warps 0-11 consume (3m x 4n, warp tile 64x32), warp 12 produces.
// ---------------------------------------------------------------------------
template<int TERMS>
__global__ __launch_bounds__(416, 1) void k_gemm_ws(
        const __grid_constant__ CUtensorMap tAh,
        const __grid_constant__ CUtensorMap tAl,
        const __grid_constant__ CUtensorMap tB,
        const float* __restrict__ bias, float* __restrict__ C,
        int Nd, unsigned long long strideC) {
    constexpr int STG = TERMS * OPA + OPBB;   // stage bytes: 64KB or 40KB
    extern __shared__ __align__(16) char dsm[];
    __shared__ __align__(8) long long mbars[2 * NST];   // full[0..2], empty[0..2]

    const int tid = threadIdx.x, wid = tid >> 5, lane = tid & 31;
    const int m0 = blockIdx.y * TM, n0 = blockIdx.x * 128, bz = blockIdx.z;
    const uint32_t tile0 = (cvta_s(dsm) + 1023u) & ~1023u;
    const uint32_t mb = cvta_s(mbars);

    if (tid == 0) {
        #pragma unroll
        for (int i = 0; i < NST; i++) {
            mbar_init(mb + i * 8, 1);                 // full: 1 expect_tx arrival
            mbar_init(mb + (NST + i) * 8, NCONS);     // empty: 12 consumer warps
        }
    }
    __syncthreads();

    if (wid == NCONS) {
        // ---------------- producer ----------------
        if (lane == 0) {
            int st = 0;
            #pragma unroll 1
            for (int s = 0; s < KTILES; s++) {
                if (s >= NST) mbar_wait(mb + (NST + st) * 8, ((s / NST) - 1) & 1);
                const uint32_t base = tile0 + st * STG;
                const uint32_t fb = mb + st * 8;
                mbar_expect(fb, STG);
                tma3d(base, &tAh, s * KSTEP, m0, bz, fb);
                if (TERMS == 2)
                    tma3d(base + OPA, &tAl, s * KSTEP, m0, bz, fb);
                tma3d(base + TERMS * OPA, &tB, s * KSTEP, n0, 0, fb);
                if (++st == NST) st = 0;
            }
        }
        return;
    }

    // ---------------- consumers ----------------
    const int warp_m = (wid >> 2) * 64, warp_n = (wid & 3) * 32;
    const int frow = lane & 15, fgh = lane >> 4;

    // per-warp row-base offsets (stage-independent)
    uint32_t roA[4], roB[2];
    #pragma unroll
    for (int i = 0; i < 4; i++) roA[i] = rowoff0(warp_m + 16 * i + frow);
    #pragma unroll
    for (int jb = 0; jb < 2; jb++) roB[jb] = rowoff0(warp_n + 16 * jb + frow);

    float acc[4][4][4];
    #pragma unroll
    for (int i = 0; i < 4; i++)
        #pragma unroll
        for (int j = 0; j < 4; j++)
            #pragma unroll
            for (int c = 0; c < 4; c++) acc[i][j][c] = 0.f;

    int st = 0;
    #pragma unroll 1
    for (int kt = 0; kt < KTILES; kt++) {
        mbar_wait(mb + st * 8, (kt / NST) & 1);
        const uint32_t base = tile0 + st * STG;
        const uint32_t sAh = base, sAl = base + OPA, sB = base + TERMS * OPA;

        #pragma unroll
        for (int k = 0; k < 4; k++) {           // four K=16 steps per stage
            const uint32_t gsh = (uint32_t)((2 * k + fgh) << 4);
            unsigned ah[4][4], al[4][4];
            #pragma unroll
            for (int i = 0; i < 4; i++) {
                ldsm4(ah[i], (sAh + roA[i]) ^ gsh);
                if (TERMS == 2) ldsm4(al[i], (sAl + roA[i]) ^ gsh);
            }
            #pragma unroll
            for (int jb = 0; jb < 2; jb++) {
                unsigned bf[4];
                ldsm4(bf, (sB + roB[jb]) ^ gsh);
                // term-outer ordering: adjacent MMAs hit distinct accumulators
                #pragma unroll
                for (int t = 0; t < TERMS; t++)
                    #pragma unroll
                    for (int jj = 0; jj < 2; jj++) {
                        const int j = jb * 2 + jj;
                        const unsigned b0 = bf[jj], b1 = bf[2 + jj];
                        #pragma unroll
                        for (int i = 0; i < 4; i++)
                            mma16816(acc[i][j], t ? al[i] : ah[i], b0, b1);
                    }
            }
        }
        if (lane == 0) mbar_arrive(mb + (NST + st) * 8);
        if (++st == NST) st = 0;
    }

    // epilogue: +bias, fp32 stores (row-guarded: M padded to 192*22)
    float* Cb = C + (size_t)bz * strideC + n0;
    const int fr = lane >> 2, fc2 = (lane & 3) * 2;
    #pragma unroll
    for (int i = 0; i < 4; i++)
        #pragma unroll
        for (int j = 0; j < 4; j++) {
            int r0 = m0 + warp_m + i * 16 + fr;
            int c0 = warp_n + j * 8 + fc2;
            float2 bv = *(const float2*)&bias[n0 + c0];
            if (r0 < NHW)
                *(float2*)&Cb[(size_t)r0 * Nd + c0] =
                    make_float2(acc[i][j][0] + bv.x, acc[i][j][1] + bv.y);
            if (r0 + 8 < NHW)
                *(float2*)&Cb[(size_t)(r0 + 8) * Nd + c0] =
                    make_float2(acc[i][j][2] + bv.x, acc[i][j][3] + bv.y);
        }
}

// ---------------------------------------------------------------------------
// Transpose [K][N] fp32 -> [N][K] fp16 hi/lo split.
// ---------------------------------------------------------------------------
__global__ void k_tsplit(const float* __restrict__ src,
                         __half* __restrict__ dh, __half* __restrict__ dl,
                         int K, int N) {
    __shared__ float t[32][33];
    const int n0 = blockIdx.x * 32, k0 = blockIdx.y * 32;
    src += (size_t)blockIdx.z * K * N;
    dh  += (size_t)blockIdx.z * N * K;
    dl  += (size_t)blockIdx.z * N * K;
    const int tx = threadIdx.x, ty = threadIdx.y;
    #pragma unroll
    for (int r = 0; r < 4; r++)
        t[ty + r * 8][tx] = src[(size_t)(k0 + ty + r * 8) * N + n0 + tx];
    __syncthreads();
    #pragma unroll
    for (int r = 0; r < 4; r++) {
        float v = t[tx][ty + r * 8];
        __half h = __float2half_rn(v);
        __half l = __float2half_rn(v - __half2float(h));
        size_t o = (size_t)(n0 + ty + r * 8) * K + k0 + tx;
        dh[o] = h;
        dl[o] = l;
    }
}

// Transpose [K][N] fp32 -> [N][K] single fp16 (weights).
__global__ void k_tsingle(const float* __restrict__ src,
                          __half* __restrict__ dh, int K, int N) {
    __shared__ float t[32][33];
    const int n0 = blockIdx.x * 32, k0 = blockIdx.y * 32;
    const int tx = threadIdx.x, ty = threadIdx.y;
    #pragma unroll
    for (int r = 0; r < 4; r++)
        t[ty + r * 8][tx] = src[(size_t)(k0 + ty + r * 8) * N + n0 + tx];
    __syncthreads();
    #pragma unroll
    for (int r = 0; r < 4; r++)
        dh[(size_t)(n0 + ty + r * 8) * K + k0 + tx] = __float2half_rn(t[tx][ty + r * 8]);
}

// ---------------------------------------------------------------------------
// Normalize q,k per token; accumulate masked/unmasked k*v partial sums.
// ---------------------------------------------------------------------------
__global__ __launch_bounds__(256) void k_normred(const float* __restrict__ mask) {
    const int b     = blockIdx.x >> 7;
    const int chunk = blockIdx.x & 127;
    const int warp  = threadIdx.x >> 5, lane = threadIdx.x & 31;

    float accK[16], accM[16];
    #pragma unroll
    for (int i = 0; i < 16; i++) { accK[i] = 0.f; accM[i] = 0.f; }

    #pragma unroll 1
    for (int it = 0; it < 4; it++) {
        const int t = chunk * 32 + warp * 4 + it;
        float* row = g_qkv + ((size_t)b * NHW + t) * NQKV;
        float q[16], kk[16], vv[16];
        float qss = 0.f, kss = 0.f;
        #pragma unroll
        for (int r = 0; r < 4; r++) {
            int c = (lane + 32 * r) * 4;
            float4 qa = *(const float4*)&row[c];
            float4 ka = *(const float4*)&row[512 + c];
            float4 va = *(const float4*)&row[1024 + c];
            q[r*4+0]=qa.x; q[r*4+1]=qa.y; q[r*4+2]=qa.z; q[r*4+3]=qa.w;
            kk[r*4+0]=ka.x; kk[r*4+1]=ka.y; kk[r*4+2]=ka.z; kk[r*4+3]=ka.w;
            vv[r*4+0]=va.x; vv[r*4+1]=va.y; vv[r*4+2]=va.z; vv[r*4+3]=va.w;
            qss += qa.x*qa.x + qa.y*qa.y + qa.z*qa.z + qa.w*qa.w;
            kss += ka.x*ka.x + ka.y*ka.y + ka.z*ka.z + ka.w*ka.w;
        }
        #pragma unroll
        for (int off = 16; off > 0; off >>= 1) {
            qss += __shfl_xor_sync(0xffffffffu, qss, off);
            kss += __shfl_xor_sync(0xffffffffu, kss, off);
        }
        const float rq = rsqrtf(qss), rk = rsqrtf(kss);
        const bool sel = mask[b * NHW + t] > 0.5f;
        #pragma unroll
        for (int i = 0; i < 16; i++) {
            float qn = q[i] * rq;
            q[i] = qn;
            float con = kk[i] * rk * vv[i];
            if (sel) accM[i] += con; else accK[i] += con;
        }
        #pragma unroll
        for (int r = 0; r < 4; r++) {
            int c = (lane + 32 * r) * 4;
            *(float4*)&row[c] = make_float4(q[r*4], q[r*4+1], q[r*4+2], q[r*4+3]);
        }
    }

    __shared__ float sh[8][1024];
    #pragma unroll
    for (int r = 0; r < 4; r++) {
        int c = (lane + 32 * r) * 4;
        *(float4*)&sh[warp][c]       = make_float4(accK[r*4], accK[r*4+1], accK[r*4+2], accK[r*4+3]);
        *(float4*)&sh[warp][512 + c] = make_float4(accM[r*4], accM[r*4+1], accM[r*4+2], accM[r*4+3]);
    }
    __syncthreads();
    float* part = g_part + (size_t)blockIdx.x * 1024;
    #pragma unroll
    for (int i = 0; i < 4; i++) {
        int ch = threadIdx.x + 256 * i;
        float s = 0.f;
        #pragma unroll
        for (int w = 0; w < 8; w++) s += sh[w][ch];
        part[ch] = s;
    }
}

__global__ void k_reduce_s() {
    const int idx = blockIdx.x * 256 + threadIdx.x;
    const int ch = idx & 1023;
    const int b = idx >> 10;
    float s = 0.f;
    for (int c2 = 0; c2 < 128; c2++)
        s += g_part[((size_t)(b * 128 + c2)) * 1024 + ch];
    if (ch >= 512) s *= 0.7f;
    g_s[idx] = s;
}

__global__ void k_scaleq(const float* __restrict__ mask) {
    const size_t idx = ((size_t)blockIdx.x * 256 + threadIdx.x) * 4;
    const int bt = (int)(idx >> 9);
    const int c  = (int)(idx & 511);
    const float4 q = *(const float4*)&g_qkv[(size_t)bt * NQKV + c];
    const bool sel = mask[bt] > 0.5f;
    const float4 sv = *(const float4*)&g_s[(bt >> 12) * 1024 + (sel ? 512 : 0) + c];
    float v[4] = {q.x * sv.x, q.y * sv.y, q.z * sv.z, q.w * sv.w};
    union { __half h[4]; uint2 u; } H;
    #pragma unroll
    for (int i = 0; i < 4; i++) H.h[i] = __float2half_rn(v[i]);
    *(uint2*)&g_qah[idx] = H.u;
}

// ---------------------------------------------------------------------------
// Host: tensormap construction via driver entry point (no -lcuda link needed)
// ---------------------------------------------------------------------------
typedef CUresult (CUDAAPI *PFN_encode)(
    CUtensorMap*, CUtensorMapDataType, cuuint32_t, void*,
    const cuuint64_t*, const cuuint64_t*, const cuuint32_t*, const cuuint32_t*,
    CUtensorMapInterleave, CUtensorMapSwizzle, CUtensorMapL2promotion,
    CUtensorMapFloatOOBfill);

static PFN_encode get_encoder() {
    static PFN_encode fn = nullptr;
    if (!fn) {
        void* p = nullptr;
        cudaDriverEntryPointQueryResult qr;
        cudaGetDriverEntryPointByVersion("cuTensorMapEncodeTiled", &p, 12000,
                                         cudaEnableDefault, &qr);
        fn = (PFN_encode)p;
    }
    return fn;
}

static void build_map(CUtensorMap* m, const void* ptr,
                      unsigned long long d1, unsigned long long d2,
                      unsigned box_rows) {
    cuuint64_t dims[3] = {NC, d1, d2};
    cuuint64_t st[2]   = {NC * 2ull, d1 * NC * 2ull};
    cuuint32_t box[3]  = {KSTEP, box_rows, 1};   // 64 fp16 = 128B rows (SW128)
    cuuint32_t es[3]   = {1, 1, 1};
    get_encoder()(m, CU_TENSOR_MAP_DATA_TYPE_FLOAT16, 3, (void*)ptr,
                  dims, st, box, es,
                  CU_TENSOR_MAP_INTERLEAVE_NONE, CU_TENSOR_MAP_SWIZZLE_128B,
                  CU_TENSOR_MAP_L2_PROMOTION_L2_128B,
                  CU_TENSOR_MAP_FLOAT_OOB_FILL_NONE);
}

extern "C" void kernel_launch(void* const* d_in, const int* in_sizes, int n_in,
                              void* d_out, int out_size) {
    const float* x    = (const float*)d_in[0];
    const float* mask = (const float*)d_in[1];
    const float* Wq   = (const float*)d_in[2];
    const float* bq   = (const float*)d_in[3];
    const float* Wo   = (const float*)d_in[4];
    const float* bo   = (const float*)d_in[5];
    float* out = (float*)d_out;

    __half *xh, *xl, *wq, *wo, *qah;
    float* qkvp;
    cudaGetSymbolAddress((void**)&xh,  g_xh);
    cudaGetSymbolAddress((void**)&xl,  g_xl);
    cudaGetSymbolAddress((void**)&wq,  g_wq);
    cudaGetSymbolAddress((void**)&wo,  g_wo);
    cudaGetSymbolAddress((void**)&qah, g_qah);
    cudaGetSymbolAddress((void**)&qkvp, g_qkv);

    CUtensorMap mXh, mXl, mWq, mQh, mWo;
    build_map(&mXh, xh,  NHW,  NB, TM);    // A tiles: 192 rows
    build_map(&mXl, xl,  NHW,  NB, TM);
    build_map(&mQh, qah, NHW,  NB, TM);
    build_map(&mWq, wq,  NQKV, 1, 128);    // B tiles: 128 rows
    build_map(&mWo, wo,  NC,   1, 128);

    const int DSMEM2T = NST * (2 * OPA + OPBB) + 1024;   // 197632
    const int DSMEM1T = NST * (OPA + OPBB) + 1024;       // 123904
    cudaFuncSetAttribute(k_gemm_ws<2>,
                         cudaFuncAttributeMaxDynamicSharedMemorySize, DSMEM2T);
    cudaFuncSetAttribute(k_gemm_ws<1>,
                         cudaFuncAttributeMaxDynamicSharedMemorySize, DSMEM1T);

    k_tsplit<<<dim3(NHW / 32, NC / 32, NB), dim3(32, 8)>>>(x, xh, xl, NC, NHW);
    k_tsingle<<<dim3(NQKV / 32, NC / 32, 1), dim3(32, 8)>>>(Wq, wq, NC, NQKV);
    k_tsingle<<<dim3(NC / 32, NC / 32, 1), dim3(32, 8)>>>(Wo, wo, NC, NC);

    // GEMM1 (2-term A): qkv = x^T @ Wqkv + bq   (M padded to 4224, N=1536, K=512)
    k_gemm_ws<2><<<dim3(NQKV / 128, MTILES, NB), 416, DSMEM2T>>>(
        mXh, mXl, mWq, bq, qkvp, NQKV, (unsigned long long)NHW * NQKV);

    k_normred<<<NB * 128, 256>>>(mask);
    k_reduce_s<<<32, 256>>>();
    k_scaleq<<<(NB * NHW * NC) / 1024, 256>>>(mask);

    // GEMM2 (1-term A): out = qA @ Wout + bo   (M padded, N=512, K=512)
    k_gemm_ws<1><<<dim3(NC / 128, MTILES, NB), 416, DSMEM1T>>>(
        mQh, mQh, mWo, bo, out, NC, (unsigned long long)NHW * NC);
}

// round 16
// speedup vs baseline: 1.8559x; 1.3664x over previous
#include <cuda_runtime.h>
#include <cuda.h>
#include <cuda_fp16.h>
#include <cstdint>

#define NB   8
#define NC   512
#define NHW  4096
#define NQKV 1536

#define KSTEP   64                      // K elems per stage = 128B rows (SW128)
#define KTILES  (NC / KSTEP)            // 8
#define TM      192                     // M tile rows (3 warp rows of 64)
#define MTILES  ((NHW + TM - 1) / TM)   // 22 (padded; TMA zero-fills OOB)
#define OPA     (TM * 128)              // A operand tile: 192 rows x 128B = 24KB
#define OPBB    (128 * 128)             // B operand tile: 128 rows x 128B = 16KB
#define NST     3
#define NCONS   12                      // consumer warps (3m x 4n)

// ---------------- scratch (__device__ globals; no allocs allowed) ----------------
__device__ float g_qkv[(size_t)NB * NHW * NQKV];
__device__ float g_part[NB * 128 * 1024];
__device__ float g_s[NB * 1024];

__device__ __align__(16) __half g_xh[(size_t)NB * NHW * NC];   // x^T fp16 [b][t][c]
__device__ __align__(16) __half g_wq[(size_t)NQKV * NC];       // Wqkv^T fp16 [j][c]
__device__ __align__(16) __half g_wo[(size_t)NC * NC];         // Wout^T fp16 [j][c]
__device__ __align__(16) __half g_qah[(size_t)NB * NHW * NC];  // scaled qn fp16

// ---------------------------------------------------------------------------
// PTX helpers (TMA / mbarrier / mma / ldmatrix)
// ---------------------------------------------------------------------------
__device__ __forceinline__ uint32_t cvta_s(const void* p) {
    return (uint32_t)__cvta_generic_to_shared(p);
}
__device__ __forceinline__ void mbar_init(uint32_t a, uint32_t c) {
    asm volatile("mbarrier.init.shared.b64 [%0], %1;" :: "r"(a), "r"(c) : "memory");
}
__device__ __forceinline__ void mbar_expect(uint32_t a, uint32_t tx) {
    asm volatile("mbarrier.arrive.expect_tx.shared.b64 _, [%0], %1;" :: "r"(a), "r"(tx) : "memory");
}
__device__ __forceinline__ void mbar_arrive(uint32_t a) {
    asm volatile("mbarrier.arrive.shared.b64 _, [%0];" :: "r"(a) : "memory");
}
__device__ __forceinline__ void mbar_wait(uint32_t a, uint32_t ph) {
    asm volatile(
        "{\n\t.reg .pred P;\n"
        "W%=:\n\tmbarrier.try_wait.parity.shared.b64 P, [%0], %1, 0x989680;\n"
        "\t@P bra D%=;\n\tbra W%=;\nD%=:\n\t}"
        :: "r"(a), "r"(ph) : "memory");
}
__device__ __forceinline__ void tma3d(uint32_t sa, const CUtensorMap* tm,
                                      int cx, int cy, int cz, uint32_t mb) {
    asm volatile(
        "cp.async.bulk.tensor.3d.shared::cta.global.tile.mbarrier::complete_tx::bytes "
        "[%0], [%1, {%2, %3, %4}], [%5];"
        :: "r"(sa), "l"(tm), "r"(cx), "r"(cy), "r"(cz), "r"(mb) : "memory");
}
__device__ __forceinline__ void mma16816(float* d, const unsigned* a, unsigned b0, unsigned b1) {
    asm volatile(
        "mma.sync.aligned.m16n8k16.row.col.f32.f16.f16.f32 "
        "{%0,%1,%2,%3}, {%4,%5,%6,%7}, {%8,%9}, {%0,%1,%2,%3};\n"
        : "+f"(d[0]), "+f"(d[1]), "+f"(d[2]), "+f"(d[3])
        : "r"(a[0]), "r"(a[1]), "r"(a[2]), "r"(a[3]), "r"(b0), "r"(b1));
}
__device__ __forceinline__ void ldsm4(unsigned* r, uint32_t addr) {
    asm volatile("ldmatrix.sync.aligned.m8n8.x4.shared.b16 {%0,%1,%2,%3}, [%4];\n"
        : "=r"(r[0]), "=r"(r[1]), "=r"(r[2]), "=r"(r[3]) : "r"(addr));
}
// SW128 row-base offset with g=0: row*128 + ((row&7)<<4).
// Full addr for granule g is (base + rowoff) ^ (g<<4)  (bases are 1024-aligned).
__device__ __forceinline__ uint32_t rowoff0(int row) {
    return (uint32_t)(row * 128 + ((row & 7) << 4));
}

// ---------------------------------------------------------------------------
// fp16 mma.sync GEMM with TMA + mbarrier pipeline.
// TERMS=2: C = (Ah+Al)·B^T + bias    TERMS=1: C = Ah·B^T + bias
// Tile 192x128, K-stage 64 (SW128), 3 stages.
// 416 threads: warps 0-11 consume (3m x 4n, warp tile 64x32), warp 12 produces.
// ---------------------------------------------------------------------------
template<int TERMS>
__global__ __launch_bounds__(416, 1) void k_gemm_ws(
        const __grid_constant__ CUtensorMap tAh,
        const __grid_constant__ CUtensorMap tAl,
        const __grid_constant__ CUtensorMap tB,
        const float* __restrict__ bias, float* __restrict__ C,
        int Nd, unsigned long long strideC) {
    constexpr int STG = TERMS * OPA + OPBB;   // stage bytes: 64KB or 40KB
    extern __shared__ __align__(16) char dsm[];
    __shared__ __align__(8) long long mbars[2 * NST];   // full[0..2], empty[0..2]

    const int tid = threadIdx.x, wid = tid >> 5, lane = tid & 31;
    const int m0 = blockIdx.y * TM, n0 = blockIdx.x * 128, bz = blockIdx.z;
    const uint32_t tile0 = (cvta_s(dsm) + 1023u) & ~1023u;
    const uint32_t mb = cvta_s(mbars);

    if (tid == 0) {
        #pragma unroll
        for (int i = 0; i < NST; i++) {
            mbar_init(mb + i * 8, 1);                 // full: 1 expect_tx arrival
            mbar_init(mb + (NST + i) * 8, NCONS);     // empty: 12 consumer warps
        }
    }
    __syncthreads();

    if (wid == NCONS) {
        // ---------------- producer ----------------
        if (lane == 0) {
            int st = 0;
            #pragma unroll 1
            for (int s = 0; s < KTILES; s++) {
                if (s >= NST) mbar_wait(mb + (NST + st) * 8, ((s / NST) - 1) & 1);
                const uint32_t base = tile0 + st * STG;
                const uint32_t fb = mb + st * 8;
                mbar_expect(fb, STG);
                tma3d(base, &tAh, s * KSTEP, m0, bz, fb);
                if (TERMS == 2)
                    tma3d(base + OPA, &tAl, s * KSTEP, m0, bz, fb);
                tma3d(base + TERMS * OPA, &tB, s * KSTEP, n0, 0, fb);
                if (++st == NST) st = 0;
            }
        }
        return;
    }

    // ---------------- consumers ----------------
    const int warp_m = (wid >> 2) * 64, warp_n = (wid & 3) * 32;
    const int frow = lane & 15, fgh = lane >> 4;

    // per-warp row-base offsets (stage-independent)
    uint32_t roA[4], roB[2];
    #pragma unroll
    for (int i = 0; i < 4; i++) roA[i] = rowoff0(warp_m + 16 * i + frow);
    #pragma unroll
    for (int jb = 0; jb < 2; jb++) roB[jb] = rowoff0(warp_n + 16 * jb + frow);

    float acc[4][4][4];
    #pragma unroll
    for (int i = 0; i < 4; i++)
        #pragma unroll
        for (int j = 0; j < 4; j++)
            #pragma unroll
            for (int c = 0; c < 4; c++) acc[i][j][c] = 0.f;

    int st = 0;
    #pragma unroll 1
    for (int kt = 0; kt < KTILES; kt++) {
        mbar_wait(mb + st * 8, (kt / NST) & 1);
        const uint32_t base = tile0 + st * STG;
        const uint32_t sAh = base, sAl = base + OPA, sB = base + TERMS * OPA;

        #pragma unroll
        for (int k = 0; k < 4; k++) {           // four K=16 steps per stage
            const uint32_t gsh = (uint32_t)((2 * k + fgh) << 4);
            unsigned ah[4][4], al[4][4];
            #pragma unroll
            for (int i = 0; i < 4; i++) {
                ldsm4(ah[i], (sAh + roA[i]) ^ gsh);
                if (TERMS == 2) ldsm4(al[i], (sAl + roA[i]) ^ gsh);
            }
            #pragma unroll
            for (int jb = 0; jb < 2; jb++) {
                unsigned bf[4];
                ldsm4(bf, (sB + roB[jb]) ^ gsh);
                // term-outer ordering: adjacent MMAs hit distinct accumulators
                #pragma unroll
                for (int t = 0; t < TERMS; t++)
                    #pragma unroll
                    for (int jj = 0; jj < 2; jj++) {
                        const int j = jb * 2 + jj;
                        const unsigned b0 = bf[jj], b1 = bf[2 + jj];
                        #pragma unroll
                        for (int i = 0; i < 4; i++)
                            mma16816(acc[i][j], t ? al[i] : ah[i], b0, b1);
                    }
            }
        }
        if (lane == 0) mbar_arrive(mb + (NST + st) * 8);
        if (++st == NST) st = 0;
    }

    // epilogue: +bias, fp32 stores (row-guarded: M padded to 192*22)
    float* Cb = C + (size_t)bz * strideC + n0;
    const int fr = lane >> 2, fc2 = (lane & 3) * 2;
    #pragma unroll
    for (int i = 0; i < 4; i++)
        #pragma unroll
        for (int j = 0; j < 4; j++) {
            int r0 = m0 + warp_m + i * 16 + fr;
            int c0 = warp_n + j * 8 + fc2;
            float2 bv = *(const float2*)&bias[n0 + c0];
            if (r0 < NHW)
                *(float2*)&Cb[(size_t)r0 * Nd + c0] =
                    make_float2(acc[i][j][0] + bv.x, acc[i][j][1] + bv.y);
            if (r0 + 8 < NHW)
                *(float2*)&Cb[(size_t)(r0 + 8) * Nd + c0] =
                    make_float2(acc[i][j][2] + bv.x, acc[i][j][3] + bv.y);
        }
}

// ---------------------------------------------------------------------------
// Transpose [K][N] fp32 -> [N][K] single fp16 (batched).
// ---------------------------------------------------------------------------
__global__ void k_tsingle(const float* __restrict__ src,
                          __half* __restrict__ dh, int K, int N) {
    __shared__ float t[32][33];
    const int n0 = blockIdx.x * 32, k0 = blockIdx.y * 32;
    src += (size_t)blockIdx.z * K * N;
    dh  += (size_t)blockIdx.z * N * K;
    const int tx = threadIdx.x, ty = threadIdx.y;
    #pragma unroll
    for (int r = 0; r < 4; r++)
        t[ty + r * 8][tx] = src[(size_t)(k0 + ty + r * 8) * N + n0 + tx];
    __syncthreads();
    #pragma unroll
    for (int r = 0; r < 4; r++)
        dh[(size_t)(n0 + ty + r * 8) * K + k0 + tx] = __float2half_rn(t[tx][ty + r * 8]);
}

// ---------------------------------------------------------------------------
// Normalize q,k per token; accumulate masked/unmasked k*v partial sums.
// ---------------------------------------------------------------------------
__global__ __launch_bounds__(256) void k_normred(const float* __restrict__ mask) {
    const int b     = blockIdx.x >> 7;
    const int chunk = blockIdx.x & 127;
    const int warp  = threadIdx.x >> 5, lane = threadIdx.x & 31;

    float accK[16], accM[16];
    #pragma unroll
    for (int i = 0; i < 16; i++) { accK[i] = 0.f; accM[i] = 0.f; }

    #pragma unroll 1
    for (int it = 0; it < 4; it++) {
        const int t = chunk * 32 + warp * 4 + it;
        float* row = g_qkv + ((size_t)b * NHW + t) * NQKV;
        float q[16], kk[16], vv[16];
        float qss = 0.f, kss = 0.f;
        #pragma unroll
        for (int r = 0; r < 4; r++) {
            int c = (lane + 32 * r) * 4;
            float4 qa = *(const float4*)&row[c];
            float4 ka = *(const float4*)&row[512 + c];
            float4 va = *(const float4*)&row[1024 + c];
            q[r*4+0]=qa.x; q[r*4+1]=qa.y; q[r*4+2]=qa.z; q[r*4+3]=qa.w;
            kk[r*4+0]=ka.x; kk[r*4+1]=ka.y; kk[r*4+2]=ka.z; kk[r*4+3]=ka.w;
            vv[r*4+0]=va.x; vv[r*4+1]=va.y; vv[r*4+2]=va.z; vv[r*4+3]=va.w;
            qss += qa.x*qa.x + qa.y*qa.y + qa.z*qa.z + qa.w*qa.w;
            kss += ka.x*ka.x + ka.y*ka.y + ka.z*ka.z + ka.w*ka.w;
        }
        #pragma unroll
        for (int off = 16; off > 0; off >>= 1) {
            qss += __shfl_xor_sync(0xffffffffu, qss, off);
            kss += __shfl_xor_sync(0xffffffffu, kss, off);
        }
        const float rq = rsqrtf(qss), rk = rsqrtf(kss);
        const bool sel = mask[b * NHW + t] > 0.5f;
        #pragma unroll
        for (int i = 0; i < 16; i++) {
            float qn = q[i] * rq;
            q[i] = qn;
            float con = kk[i] * rk * vv[i];
            if (sel) accM[i] += con; else accK[i] += con;
        }
        #pragma unroll
        for (int r = 0; r < 4; r++) {
            int c = (lane + 32 * r) * 4;
            *(float4*)&row[c] = make_float4(q[r*4], q[r*4+1], q[r*4+2], q[r*4+3]);
        }
    }

    __shared__ float sh[8][1024];
    #pragma unroll
    for (int r = 0; r < 4; r++) {
        int c = (lane + 32 * r) * 4;
        *(float4*)&sh[warp][c]       = make_float4(accK[r*4], accK[r*4+1], accK[r*4+2], accK[r*4+3]);
        *(float4*)&sh[warp][512 + c] = make_float4(accM[r*4], accM[r*4+1], accM[r*4+2], accM[r*4+3]);
    }
    __syncthreads();
    float* part = g_part + (size_t)blockIdx.x * 1024;
    #pragma unroll
    for (int i = 0; i < 4; i++) {
        int ch = threadIdx.x + 256 * i;
        float s = 0.f;
        #pragma unroll
        for (int w = 0; w < 8; w++) s += sh[w][ch];
        part[ch] = s;
    }
}

__global__ void k_reduce_s() {
    const int idx = blockIdx.x * 256 + threadIdx.x;
    const int ch = idx & 1023;
    const int b = idx >> 10;
    float s = 0.f;
    for (int c2 = 0; c2 < 128; c2++)
        s += g_part[((size_t)(b * 128 + c2)) * 1024 + ch];
    if (ch >= 512) s *= 0.7f;
    g_s[idx] = s;
}

__global__ void k_scaleq(const float* __restrict__ mask) {
    const size_t idx = ((size_t)blockIdx.x * 256 + threadIdx.x) * 4;
    const int bt = (int)(idx >> 9);
    const int c  = (int)(idx & 511);
    const float4 q = *(const float4*)&g_qkv[(size_t)bt * NQKV + c];
    const bool sel = mask[bt] > 0.5f;
    const float4 sv = *(const float4*)&g_s[(bt >> 12) * 1024 + (sel ? 512 : 0) + c];
    float v[4] = {q.x * sv.x, q.y * sv.y, q.z * sv.z, q.w * sv.w};
    union { __half h[4]; uint2 u; } H;
    #pragma unroll
    for (int i = 0; i < 4; i++) H.h[i] = __float2half_rn(v[i]);
    *(uint2*)&g_qah[idx] = H.u;
}

// ---------------------------------------------------------------------------
// Host: tensormap construction via driver entry point (no -lcuda link needed)
// ---------------------------------------------------------------------------
typedef CUresult (CUDAAPI *PFN_encode)(
    CUtensorMap*, CUtensorMapDataType, cuuint32_t, void*,
    const cuuint64_t*, const cuuint64_t*, const cuuint32_t*, const cuuint32_t*,
    CUtensorMapInterleave, CUtensorMapSwizzle, CUtensorMapL2promotion,
    CUtensorMapFloatOOBfill);

static PFN_encode get_encoder() {
    static PFN_encode fn = nullptr;
    if (!fn) {
        void* p = nullptr;
        cudaDriverEntryPointQueryResult qr;
        cudaGetDriverEntryPointByVersion("cuTensorMapEncodeTiled", &p, 12000,
                                         cudaEnableDefault, &qr);
        fn = (PFN_encode)p;
    }
    return fn;
}

static void build_map(CUtensorMap* m, const void* ptr,
                      unsigned long long d1, unsigned long long d2,
                      unsigned box_rows) {
    cuuint64_t dims[3] = {NC, d1, d2};
    cuuint64_t st[2]   = {NC * 2ull, d1 * NC * 2ull};
    cuuint32_t box[3]  = {KSTEP, box_rows, 1};   // 64 fp16 = 128B rows (SW128)
    cuuint32_t es[3]   = {1, 1, 1};
    get_encoder()(m, CU_TENSOR_MAP_DATA_TYPE_FLOAT16, 3, (void*)ptr,
                  dims, st, box, es,
                  CU_TENSOR_MAP_INTERLEAVE_NONE, CU_TENSOR_MAP_SWIZZLE_128B,
                  CU_TENSOR_MAP_L2_PROMOTION_L2_128B,
                  CU_TENSOR_MAP_FLOAT_OOB_FILL_NONE);
}

extern "C" void kernel_launch(void* const* d_in, const int* in_sizes, int n_in,
                              void* d_out, int out_size) {
    const float* x    = (const float*)d_in[0];
    const float* mask = (const float*)d_in[1];
    const float* Wq   = (const float*)d_in[2];
    const float* bq   = (const float*)d_in[3];
    const float* Wo   = (const float*)d_in[4];
    const float* bo   = (const float*)d_in[5];
    float* out = (float*)d_out;

    __half *xh, *wq, *wo, *qah;
    float* qkvp;
    cudaGetSymbolAddress((void**)&xh,  g_xh);
    cudaGetSymbolAddress((void**)&wq,  g_wq);
    cudaGetSymbolAddress((void**)&wo,  g_wo);
    cudaGetSymbolAddress((void**)&qah, g_qah);
    cudaGetSymbolAddress((void**)&qkvp, g_qkv);

    CUtensorMap mXh, mWq, mQh, mWo;
    build_map(&mXh, xh,  NHW,  NB, TM);    // A tiles: 192 rows
    build_map(&mQh, qah, NHW,  NB, TM);
    build_map(&mWq, wq,  NQKV, 1, 128);    // B tiles: 128 rows
    build_map(&mWo, wo,  NC,   1, 128);

    const int DSMEM1T = NST * (OPA + OPBB) + 1024;       // 123904
    cudaFuncSetAttribute(k_gemm_ws<1>,
                         cudaFuncAttributeMaxDynamicSharedMemorySize, DSMEM1T);

    k_tsingle<<<dim3(NHW / 32, NC / 32, NB), dim3(32, 8)>>>(x, xh, NC, NHW);
    k_tsingle<<<dim3(NQKV / 32, NC / 32, 1), dim3(32, 8)>>>(Wq, wq, NC, NQKV);
    k_tsingle<<<dim3(NC / 32, NC / 32, 1), dim3(32, 8)>>>(Wo, wo, NC, NC);

    // GEMM1 (1-term fp16 A): qkv = x^T @ Wqkv + bq   (M padded to 4224, N=1536, K=512)
    k_gemm_ws<1><<<dim3(NQKV / 128, MTILES, NB), 416, DSMEM1T>>>(
        mXh, mXh, mWq, bq, qkvp, NQKV, (unsigned long long)NHW * NQKV);

    k_normred<<<NB * 128, 256>>>(mask);
    k_reduce_s<<<32, 256>>>();
    k_scaleq<<<(NB * NHW * NC) / 1024, 256>>>(mask);

    // GEMM2 (1-term fp16 A): out = qA @ Wout + bo   (M padded, N=512, K=512)
    k_gemm_ws<1><<<dim3(NC / 128, MTILES, NB), 416, DSMEM1T>>>(
        mQh, mQh, mWo, bo, out, NC, (unsigned long long)NHW * NC);
}